// round 11
// baseline (speedup 1.0000x reference)
#include <cuda_runtime.h>
#include <cuda_fp16.h>

#define N_FEAT_COLS 9
#define CARD 50000
#define EMB 128
#define EDGE_DIM 27
#define TBL_ELEMS (N_FEAT_COLS * CARD * EMB)   // 57,600,000

// fp16 shadow of emb_feats (115.2 MB static device scratch)
__device__ __half g_tbl[TBL_ELEMS];

__device__ float g_v[EDGE_DIM];
__device__ float g_c;

#define CONV_BLOCK 1024
#define CONV_PER_THREAD 4   // floats per thread

// Fused: fp32->fp16 table conversion everywhere; block 0 additionally
// computes g_v / g_c (warp j -> g_v[j], warp 27 -> g_c). The extra work in
// block 0 is noise across ~14k blocks.
__global__ __launch_bounds__(CONV_BLOCK)
void convert_kernel(const float* __restrict__ src,
                    const float* __restrict__ edge_w,
                    const float* __restrict__ edge_b,
                    const float* __restrict__ out_w,
                    const float* __restrict__ out_b) {
    if (blockIdx.x == 0) {
        const unsigned FULL = 0xffffffffu;
        int w = threadIdx.x >> 5;
        int lane = threadIdx.x & 31;
        if (w <= EDGE_DIM) {
            float s = 0.f;
            if (w < EDGE_DIM) {
                for (int k = lane; k < EMB; k += 32)
                    s += out_w[k] * edge_w[k * EDGE_DIM + w];
            } else {
                for (int k = lane; k < EMB; k += 32)
                    s += out_w[k] * edge_b[k];
            }
            #pragma unroll
            for (int o = 16; o > 0; o >>= 1) s += __shfl_xor_sync(FULL, s, o);
            if (lane == 0) {
                if (w < EDGE_DIM) g_v[w] = s;
                else              g_c = s + out_b[0];
            }
        }
    }
    long long i = ((long long)blockIdx.x * CONV_BLOCK + threadIdx.x) * CONV_PER_THREAD;
    if (i >= TBL_ELEMS) return;
    float4 v = __ldcs(reinterpret_cast<const float4*>(src + i));
    __half2 lo = __floats2half2_rn(v.x, v.y);
    __half2 hi = __floats2half2_rn(v.z, v.w);
    uint2 u;
    u.x = *reinterpret_cast<unsigned*>(&lo);
    u.y = *reinterpret_cast<unsigned*>(&hi);
    *reinterpret_cast<uint2*>(g_tbl + i) = u;
}

__device__ __forceinline__ float4 ld4(const float* __restrict__ p) {
    return *reinterpret_cast<const float4*>(p);
}

__device__ __forceinline__ void acc_u2(float4& a, uint2 u) {
    __half2 h0 = *reinterpret_cast<__half2*>(&u.x);
    __half2 h1 = *reinterpret_cast<__half2*>(&u.y);
    float2 f0 = __half22float2(h0);
    float2 f1 = __half22float2(h1);
    a.x += f0.x; a.y += f0.y; a.z += f1.x; a.w += f1.y;
}

// Issue the (up to) 4 table gathers for one node; results land in g[4].
__device__ __forceinline__ void issue_node(uint2* g, int h0, int nh,
                                           const int* f, int lane4) {
    const uint2 z = make_uint2(0u, 0u);
    #pragma unroll
    for (int i = 0; i < 4; i++) {
        const __half* p = g_tbl + ((long long)(h0 + i) * CARD + f[i]) * EMB + lane4;
        g[i] = (i < nh) ? __ldg(reinterpret_cast<const uint2*>(p)) : z;
    }
}

__global__ __launch_bounds__(256)
void edge_pred_kernel(const int* __restrict__ x,
                      const int* __restrict__ src,
                      const int* __restrict__ dst,
                      const int* __restrict__ neg_dst,
                      const float* __restrict__ msg,
                      const float* __restrict__ emb_type,
                      const float* __restrict__ out_w,
                      float* __restrict__ out,
                      int E) {
    const unsigned FULL = 0xffffffffu;
    int warp = (blockIdx.x * blockDim.x + threadIdx.x) >> 5;
    int lane = threadIdx.x & 31;
    if (warp >= E) return;
    int e = warp;
    int lane4 = lane * 4;

    int s  = __ldcs(src + e);
    int d  = __ldcs(dst + e);
    int nd = __ldcs(neg_dst + e);

    // Lanes 0..29 cooperatively load the three 10-int x rows.
    int which = lane / 10;          // 0:src 1:dst 2:neg
    int off   = lane - which * 10;
    int nid   = (which == 0) ? s : (which == 1) ? d : nd;
    int rv = 0;
    if (lane < 30) rv = __ldcs(x + (long long)nid * 10 + off);

    // msg dot with precomputed v (streaming; independent)
    float m = 0.f;
    if (lane < EDGE_DIM)
        m = __ldcs(msg + (long long)e * EDGE_DIM + lane) * g_v[lane];

    // ---- all types / feature indices up front (shuffles only) ----
    int t0 = __shfl_sync(FULL, rv, 0);
    int t1 = __shfl_sync(FULL, rv, 10);
    int t2 = __shfl_sync(FULL, rv, 20);
    // TYPE_PER_COL = (0,0,0,0,1,2,2,2,2)
    int h00 = (t0 == 0) ? 0 : (t0 == 1) ? 4 : 5;
    int h01 = (t1 == 0) ? 0 : (t1 == 1) ? 4 : 5;
    int h02 = (t2 == 0) ? 0 : (t2 == 1) ? 4 : 5;
    int nh0 = (t0 == 1) ? 1 : 4;
    int nh1 = (t1 == 1) ? 1 : 4;
    int nh2 = (t2 == 1) ? 1 : 4;

    int f0[4], f1[4], f2[4];
    #pragma unroll
    for (int i = 0; i < 4; i++) {
        f0[i] = __shfl_sync(FULL, rv,      h00 + i + 1);
        f1[i] = __shfl_sync(FULL, rv, 10 + h01 + i + 1);
        f2[i] = __shfl_sync(FULL, rv, 20 + h02 + i + 1);
    }

    // ---- two-node-deep pipeline: gathers of node i+1 in flight while
    //      accumulating node i (fp16 results are cheap: uint2 each) ----
    float4 a0 = ld4(emb_type + t0 * EMB + lane4);
    float4 a1 = ld4(emb_type + t1 * EMB + lane4);
    float4 a2 = ld4(emb_type + t2 * EMB + lane4);

    uint2 gA[4], gB[4];
    issue_node(gA, h00, nh0, f0, lane4);          // node0 in flight
    issue_node(gB, h01, nh1, f1, lane4);          // node1 in flight
    #pragma unroll
    for (int i = 0; i < 4; i++) acc_u2(a0, gA[i]); // consume node0
    issue_node(gA, h02, nh2, f2, lane4);          // node2 in flight
    #pragma unroll
    for (int i = 0; i < 4; i++) acc_u2(a1, gB[i]); // consume node1
    #pragma unroll
    for (int i = 0; i < 4; i++) acc_u2(a2, gA[i]); // consume node2

    float4 ow = ld4(out_w + lane4);

    float pp = fmaxf(a0.x + a1.x, 0.f) * ow.x
             + fmaxf(a0.y + a1.y, 0.f) * ow.y
             + fmaxf(a0.z + a1.z, 0.f) * ow.z
             + fmaxf(a0.w + a1.w, 0.f) * ow.w;
    float np = fmaxf(a0.x + a2.x, 0.f) * ow.x
             + fmaxf(a0.y + a2.y, 0.f) * ow.y
             + fmaxf(a0.z + a2.z, 0.f) * ow.z
             + fmaxf(a0.w + a2.w, 0.f) * ow.w;

    pp += m;
    np += m;

    #pragma unroll
    for (int o = 16; o > 0; o >>= 1) {
        pp += __shfl_xor_sync(FULL, pp, o);
        np += __shfl_xor_sync(FULL, np, o);
    }

    if (lane == 0) {
        float c = g_c;
        out[e]     = pp + c;   // pos
        out[E + e] = np + c;   // neg
    }
}

extern "C" void kernel_launch(void* const* d_in, const int* in_sizes, int n_in,
                              void* d_out, int out_size) {
    const int*   x        = (const int*)  d_in[0];
    const int*   src      = (const int*)  d_in[1];
    const int*   dst      = (const int*)  d_in[2];
    const int*   neg_dst  = (const int*)  d_in[3];
    const float* msg      = (const float*)d_in[4];
    const float* emb_type = (const float*)d_in[5];
    const float* emb_feats= (const float*)d_in[6];
    const float* edge_w   = (const float*)d_in[7];
    const float* edge_b   = (const float*)d_in[8];
    const float* out_w    = (const float*)d_in[9];
    const float* out_b    = (const float*)d_in[10];
    float* out = (float*)d_out;

    int E = in_sizes[1];

    // Fused convert + precompute (one launch)
    long long conv_items = (TBL_ELEMS + CONV_PER_THREAD - 1) / CONV_PER_THREAD;
    int conv_blocks = (int)((conv_items + CONV_BLOCK - 1) / CONV_BLOCK);
    convert_kernel<<<conv_blocks, CONV_BLOCK>>>(emb_feats, edge_w, edge_b,
                                                out_w, out_b);

    int threads = 256;
    int warps_per_block = threads / 32;
    int blocks = (E + warps_per_block - 1) / warps_per_block;
    edge_pred_kernel<<<blocks, threads>>>(x, src, dst, neg_dst, msg,
                                          emb_type, out_w, out, E);
}

// round 12
// speedup vs baseline: 1.1560x; 1.1560x over previous
#include <cuda_runtime.h>
#include <cuda_fp16.h>

#define N_FEAT_COLS 9
#define CARD 50000
#define EMB 128
#define EDGE_DIM 27
#define TBL_ELEMS (N_FEAT_COLS * CARD * EMB)   // 57,600,000
#define TBL_COL_BYTES (CARD * EMB * 2)         // 12,800,000 bytes per column table

// fp16 shadow of emb_feats (115.2 MB static device scratch)
__device__ __half g_tbl[TBL_ELEMS];

__device__ float g_v[EDGE_DIM];
__device__ float g_c;

#define CONV_BLOCK 256
#define CONV_PER_THREAD 4   // floats per thread

// Fused: fp32->fp16 table conversion everywhere; block 0 warps also compute
// g_v / g_c (warp j -> g_v[j], warp 27 on block 1 handles g_c to stay in 8 warps).
__global__ __launch_bounds__(CONV_BLOCK)
void convert_kernel(const float* __restrict__ src,
                    const float* __restrict__ edge_w,
                    const float* __restrict__ edge_b,
                    const float* __restrict__ out_w,
                    const float* __restrict__ out_b) {
    if (blockIdx.x < 4) {
        // 4 blocks x 8 warps = 32 warps; warps 0..26 -> g_v, warp 27 -> g_c
        const unsigned FULL = 0xffffffffu;
        int w = (blockIdx.x << 3) + (threadIdx.x >> 5);
        int lane = threadIdx.x & 31;
        if (w <= EDGE_DIM) {
            float s = 0.f;
            if (w < EDGE_DIM) {
                for (int k = lane; k < EMB; k += 32)
                    s += out_w[k] * edge_w[k * EDGE_DIM + w];
            } else {
                for (int k = lane; k < EMB; k += 32)
                    s += out_w[k] * edge_b[k];
            }
            #pragma unroll
            for (int o = 16; o > 0; o >>= 1) s += __shfl_xor_sync(FULL, s, o);
            if (lane == 0) {
                if (w < EDGE_DIM) g_v[w] = s;
                else              g_c = s + out_b[0];
            }
        }
    }
    long long i = ((long long)blockIdx.x * CONV_BLOCK + threadIdx.x) * CONV_PER_THREAD;
    if (i >= TBL_ELEMS) return;
    float4 v = __ldcs(reinterpret_cast<const float4*>(src + i));
    __half2 lo = __floats2half2_rn(v.x, v.y);
    __half2 hi = __floats2half2_rn(v.z, v.w);
    uint2 u;
    u.x = *reinterpret_cast<unsigned*>(&lo);
    u.y = *reinterpret_cast<unsigned*>(&hi);
    *reinterpret_cast<uint2*>(g_tbl + i) = u;
}

__device__ __forceinline__ float4 ld4(const float* __restrict__ p) {
    return *reinterpret_cast<const float4*>(p);
}

__device__ __forceinline__ void acc_u2(float4& a, uint2 u) {
    __half2 h0 = *reinterpret_cast<__half2*>(&u.x);
    __half2 h1 = *reinterpret_cast<__half2*>(&u.y);
    float2 f0 = __half22float2(h0);
    float2 f1 = __half22float2(h1);
    a.x += f0.x; a.y += f0.y; a.z += f1.x; a.w += f1.y;
}

// Issue the (up to) 4 table gathers for one node with 32-bit byte offsets.
// off = h * TBL_COL_BYTES + f * 256 + lane*8  (max 115.2e6 < 2^32)
__device__ __forceinline__ void issue_node(uint2* g, int h0, int nh,
                                           const int* f, unsigned lane8,
                                           const char* __restrict__ tbl) {
    const uint2 z = make_uint2(0u, 0u);
    #pragma unroll
    for (int i = 0; i < 4; i++) {
        unsigned off = (unsigned)(h0 + i) * (unsigned)TBL_COL_BYTES
                     + ((unsigned)f[i] << 8) + lane8;
        g[i] = (i < nh) ? __ldg(reinterpret_cast<const uint2*>(tbl + off)) : z;
    }
}

__global__ __launch_bounds__(256)
void edge_pred_kernel(const int* __restrict__ x,
                      const int* __restrict__ src,
                      const int* __restrict__ dst,
                      const int* __restrict__ neg_dst,
                      const float* __restrict__ msg,
                      const float* __restrict__ emb_type,
                      const float* __restrict__ out_w,
                      float* __restrict__ out,
                      int E) {
    const unsigned FULL = 0xffffffffu;
    int warp = (blockIdx.x * blockDim.x + threadIdx.x) >> 5;
    int lane = threadIdx.x & 31;
    if (warp >= E) return;
    int e = warp;
    int lane4 = lane * 4;
    unsigned lane8 = (unsigned)lane * 8u;
    const char* tbl = reinterpret_cast<const char*>(g_tbl);

    int s  = __ldcs(src + e);
    int d  = __ldcs(dst + e);
    int nd = __ldcs(neg_dst + e);

    // Lanes 0..29 cooperatively load the three 10-int x rows.
    int which = lane / 10;          // 0:src 1:dst 2:neg
    int off   = lane - which * 10;
    int nid   = (which == 0) ? s : (which == 1) ? d : nd;
    int rv = 0;
    if (lane < 30) rv = __ldcs(x + (long long)nid * 10 + off);

    // msg dot with precomputed v (streaming; independent)
    float m = 0.f;
    if (lane < EDGE_DIM)
        m = __ldcs(msg + (long long)e * EDGE_DIM + lane) * g_v[lane];

    // ---- all types / feature indices up front (shuffles only) ----
    int t0 = __shfl_sync(FULL, rv, 0);
    int t1 = __shfl_sync(FULL, rv, 10);
    int t2 = __shfl_sync(FULL, rv, 20);
    // TYPE_PER_COL = (0,0,0,0,1,2,2,2,2)
    int h00 = (t0 == 0) ? 0 : (t0 == 1) ? 4 : 5;
    int h01 = (t1 == 0) ? 0 : (t1 == 1) ? 4 : 5;
    int h02 = (t2 == 0) ? 0 : (t2 == 1) ? 4 : 5;
    int nh0 = (t0 == 1) ? 1 : 4;
    int nh1 = (t1 == 1) ? 1 : 4;
    int nh2 = (t2 == 1) ? 1 : 4;

    int f0[4], f1[4], f2[4];
    #pragma unroll
    for (int i = 0; i < 4; i++) {
        f0[i] = __shfl_sync(FULL, rv,      h00 + i + 1);
        f1[i] = __shfl_sync(FULL, rv, 10 + h01 + i + 1);
        f2[i] = __shfl_sync(FULL, rv, 20 + h02 + i + 1);
    }

    // ---- two-node-deep pipeline (unchanged: measured win in R10) ----
    float4 a0 = ld4(emb_type + t0 * EMB + lane4);
    float4 a1 = ld4(emb_type + t1 * EMB + lane4);
    float4 a2 = ld4(emb_type + t2 * EMB + lane4);

    uint2 gA[4], gB[4];
    issue_node(gA, h00, nh0, f0, lane8, tbl);      // node0 in flight
    issue_node(gB, h01, nh1, f1, lane8, tbl);      // node1 in flight
    #pragma unroll
    for (int i = 0; i < 4; i++) acc_u2(a0, gA[i]); // consume node0
    issue_node(gA, h02, nh2, f2, lane8, tbl);      // node2 in flight
    #pragma unroll
    for (int i = 0; i < 4; i++) acc_u2(a1, gB[i]); // consume node1
    #pragma unroll
    for (int i = 0; i < 4; i++) acc_u2(a2, gA[i]); // consume node2

    float4 ow = ld4(out_w + lane4);

    float pp = fmaxf(a0.x + a1.x, 0.f) * ow.x
             + fmaxf(a0.y + a1.y, 0.f) * ow.y
             + fmaxf(a0.z + a1.z, 0.f) * ow.z
             + fmaxf(a0.w + a1.w, 0.f) * ow.w;
    float np = fmaxf(a0.x + a2.x, 0.f) * ow.x
             + fmaxf(a0.y + a2.y, 0.f) * ow.y
             + fmaxf(a0.z + a2.z, 0.f) * ow.z
             + fmaxf(a0.w + a2.w, 0.f) * ow.w;

    pp += m;
    np += m;

    // ---- split half-warp reduction: lanes 0..15 reduce pp, 16..31 reduce np
    pp += __shfl_xor_sync(FULL, pp, 16);
    np += __shfl_xor_sync(FULL, np, 16);
    float v = (lane < 16) ? pp : np;
    #pragma unroll
    for (int o = 8; o > 0; o >>= 1)
        v += __shfl_xor_sync(FULL, v, o);

    if (lane == 0)  out[e]     = v + g_c;   // pos
    if (lane == 16) out[E + e] = v + g_c;   // neg
}

extern "C" void kernel_launch(void* const* d_in, const int* in_sizes, int n_in,
                              void* d_out, int out_size) {
    const int*   x        = (const int*)  d_in[0];
    const int*   src      = (const int*)  d_in[1];
    const int*   dst      = (const int*)  d_in[2];
    const int*   neg_dst  = (const int*)  d_in[3];
    const float* msg      = (const float*)d_in[4];
    const float* emb_type = (const float*)d_in[5];
    const float* emb_feats= (const float*)d_in[6];
    const float* edge_w   = (const float*)d_in[7];
    const float* edge_b   = (const float*)d_in[8];
    const float* out_w    = (const float*)d_in[9];
    const float* out_b    = (const float*)d_in[10];
    float* out = (float*)d_out;

    int E = in_sizes[1];

    // Fused convert + precompute (one launch)
    long long conv_items = (TBL_ELEMS + CONV_PER_THREAD - 1) / CONV_PER_THREAD;
    int conv_blocks = (int)((conv_items + CONV_BLOCK - 1) / CONV_BLOCK);
    convert_kernel<<<conv_blocks, CONV_BLOCK>>>(emb_feats, edge_w, edge_b,
                                                out_w, out_b);

    int threads = 256;
    int warps_per_block = threads / 32;
    int blocks = (E + warps_per_block - 1) / warps_per_block;
    edge_pred_kernel<<<blocks, threads>>>(x, src, dst, neg_dst, msg,
                                          emb_type, out_w, out, E);
}

// round 13
// speedup vs baseline: 1.1969x; 1.0354x over previous
#include <cuda_runtime.h>
#include <cuda_fp16.h>

#define N_FEAT_COLS 9
#define CARD 50000
#define EMB 128
#define EDGE_DIM 27
#define TBL_ELEMS (N_FEAT_COLS * CARD * EMB)   // 57,600,000
#define TBL_COL_BYTES (CARD * EMB * 2)         // 12,800,000 bytes per column table

// fp16 shadow of emb_feats (115.2 MB static device scratch)
__device__ __half g_tbl[TBL_ELEMS];

__device__ float g_v[EDGE_DIM];
__device__ float g_c;

#define CONV_BLOCK 256
#define CONV_PER_THREAD 4   // floats per thread

// Fused: fp32->fp16 table conversion everywhere; first 4 blocks' warps also
// compute g_v / g_c (32 warps: 0..26 -> g_v, 27 -> g_c).
__global__ __launch_bounds__(CONV_BLOCK)
void convert_kernel(const float* __restrict__ src,
                    const float* __restrict__ edge_w,
                    const float* __restrict__ edge_b,
                    const float* __restrict__ out_w,
                    const float* __restrict__ out_b) {
    if (blockIdx.x < 4) {
        const unsigned FULL = 0xffffffffu;
        int w = (blockIdx.x << 3) + (threadIdx.x >> 5);
        int lane = threadIdx.x & 31;
        if (w <= EDGE_DIM) {
            float s = 0.f;
            if (w < EDGE_DIM) {
                for (int k = lane; k < EMB; k += 32)
                    s += out_w[k] * edge_w[k * EDGE_DIM + w];
            } else {
                for (int k = lane; k < EMB; k += 32)
                    s += out_w[k] * edge_b[k];
            }
            #pragma unroll
            for (int o = 16; o > 0; o >>= 1) s += __shfl_xor_sync(FULL, s, o);
            if (lane == 0) {
                if (w < EDGE_DIM) g_v[w] = s;
                else              g_c = s + out_b[0];
            }
        }
    }
    long long i = ((long long)blockIdx.x * CONV_BLOCK + threadIdx.x) * CONV_PER_THREAD;
    if (i >= TBL_ELEMS) return;
    float4 v = __ldcs(reinterpret_cast<const float4*>(src + i));
    __half2 lo = __floats2half2_rn(v.x, v.y);
    __half2 hi = __floats2half2_rn(v.z, v.w);
    uint2 u;
    u.x = *reinterpret_cast<unsigned*>(&lo);
    u.y = *reinterpret_cast<unsigned*>(&hi);
    *reinterpret_cast<uint2*>(g_tbl + i) = u;
}

__device__ __forceinline__ float4 ld4(const float* __restrict__ p) {
    return *reinterpret_cast<const float4*>(p);
}

__device__ __forceinline__ __half2 u2h(unsigned u) {
    return *reinterpret_cast<__half2*>(&u);
}

// Issue the (up to) 4 table gathers for one node with 32-bit byte offsets.
__device__ __forceinline__ void issue_node(uint2* g, int h0, int nh,
                                           const int* f, unsigned lane8,
                                           const char* __restrict__ tbl) {
    const uint2 z = make_uint2(0u, 0u);
    #pragma unroll
    for (int i = 0; i < 4; i++) {
        unsigned off = (unsigned)(h0 + i) * (unsigned)TBL_COL_BYTES
                     + ((unsigned)f[i] << 8) + lane8;
        g[i] = (i < nh) ? __ldg(reinterpret_cast<const uint2*>(tbl + off)) : z;
    }
}

// Consume 4 gather results: pairwise fp16 tree sum, one convert, fp32 add.
// (zeros from predicated-out gathers add exactly; <=2 fp16 roundings/element)
__device__ __forceinline__ void consume_node(float4& a, const uint2* g) {
    __half2 lo = __hadd2(__hadd2(u2h(g[0].x), u2h(g[1].x)),
                         __hadd2(u2h(g[2].x), u2h(g[3].x)));
    __half2 hi = __hadd2(__hadd2(u2h(g[0].y), u2h(g[1].y)),
                         __hadd2(u2h(g[2].y), u2h(g[3].y)));
    float2 flo = __half22float2(lo);
    float2 fhi = __half22float2(hi);
    a.x += flo.x; a.y += flo.y; a.z += fhi.x; a.w += fhi.y;
}

__global__ __launch_bounds__(256)
void edge_pred_kernel(const int* __restrict__ x,
                      const int* __restrict__ src,
                      const int* __restrict__ dst,
                      const int* __restrict__ neg_dst,
                      const float* __restrict__ msg,
                      const float* __restrict__ emb_type,
                      const float* __restrict__ out_w,
                      float* __restrict__ out,
                      int E) {
    const unsigned FULL = 0xffffffffu;
    int warp = (blockIdx.x * blockDim.x + threadIdx.x) >> 5;
    int lane = threadIdx.x & 31;
    if (warp >= E) return;
    int e = warp;
    int lane4 = lane * 4;
    unsigned lane8 = (unsigned)lane * 8u;
    const char* tbl = reinterpret_cast<const char*>(g_tbl);

    int s  = __ldcs(src + e);
    int d  = __ldcs(dst + e);
    int nd = __ldcs(neg_dst + e);

    // Lanes 0..29 cooperatively load the three 10-int x rows.
    int which = lane / 10;          // 0:src 1:dst 2:neg
    int off   = lane - which * 10;
    int nid   = (which == 0) ? s : (which == 1) ? d : nd;
    int rv = 0;
    if (lane < 30) rv = __ldcs(x + (long long)nid * 10 + off);

    // msg dot with precomputed v (streaming; independent)
    float m = 0.f;
    if (lane < EDGE_DIM)
        m = __ldcs(msg + (long long)e * EDGE_DIM + lane) * g_v[lane];

    // ---- all types / feature indices up front (shuffles only) ----
    int t0 = __shfl_sync(FULL, rv, 0);
    int t1 = __shfl_sync(FULL, rv, 10);
    int t2 = __shfl_sync(FULL, rv, 20);
    // TYPE_PER_COL = (0,0,0,0,1,2,2,2,2)
    int h00 = (t0 == 0) ? 0 : (t0 == 1) ? 4 : 5;
    int h01 = (t1 == 0) ? 0 : (t1 == 1) ? 4 : 5;
    int h02 = (t2 == 0) ? 0 : (t2 == 1) ? 4 : 5;
    int nh0 = (t0 == 1) ? 1 : 4;
    int nh1 = (t1 == 1) ? 1 : 4;
    int nh2 = (t2 == 1) ? 1 : 4;

    int f0[4], f1[4], f2[4];
    #pragma unroll
    for (int i = 0; i < 4; i++) {
        f0[i] = __shfl_sync(FULL, rv,      h00 + i + 1);
        f1[i] = __shfl_sync(FULL, rv, 10 + h01 + i + 1);
        f2[i] = __shfl_sync(FULL, rv, 20 + h02 + i + 1);
    }

    // ---- two-node-deep pipeline (memory shape unchanged from R10/R12) ----
    float4 a0 = ld4(emb_type + t0 * EMB + lane4);
    float4 a1 = ld4(emb_type + t1 * EMB + lane4);
    float4 a2 = ld4(emb_type + t2 * EMB + lane4);

    uint2 gA[4], gB[4];
    issue_node(gA, h00, nh0, f0, lane8, tbl);   // node0 in flight
    issue_node(gB, h01, nh1, f1, lane8, tbl);   // node1 in flight
    consume_node(a0, gA);                       // consume node0
    issue_node(gA, h02, nh2, f2, lane8, tbl);   // node2 in flight
    consume_node(a1, gB);                       // consume node1
    consume_node(a2, gA);                       // consume node2

    float4 ow = ld4(out_w + lane4);

    float pp = fmaxf(a0.x + a1.x, 0.f) * ow.x
             + fmaxf(a0.y + a1.y, 0.f) * ow.y
             + fmaxf(a0.z + a1.z, 0.f) * ow.z
             + fmaxf(a0.w + a1.w, 0.f) * ow.w;
    float np = fmaxf(a0.x + a2.x, 0.f) * ow.x
             + fmaxf(a0.y + a2.y, 0.f) * ow.y
             + fmaxf(a0.z + a2.z, 0.f) * ow.z
             + fmaxf(a0.w + a2.w, 0.f) * ow.w;

    pp += m;
    np += m;

    // ---- split half-warp reduction: lanes 0..15 reduce pp, 16..31 reduce np
    pp += __shfl_xor_sync(FULL, pp, 16);
    np += __shfl_xor_sync(FULL, np, 16);
    float v = (lane < 16) ? pp : np;
    #pragma unroll
    for (int o = 8; o > 0; o >>= 1)
        v += __shfl_xor_sync(FULL, v, o);

    if (lane == 0)  out[e]     = v + g_c;   // pos
    if (lane == 16) out[E + e] = v + g_c;   // neg
}

extern "C" void kernel_launch(void* const* d_in, const int* in_sizes, int n_in,
                              void* d_out, int out_size) {
    const int*   x        = (const int*)  d_in[0];
    const int*   src      = (const int*)  d_in[1];
    const int*   dst      = (const int*)  d_in[2];
    const int*   neg_dst  = (const int*)  d_in[3];
    const float* msg      = (const float*)d_in[4];
    const float* emb_type = (const float*)d_in[5];
    const float* emb_feats= (const float*)d_in[6];
    const float* edge_w   = (const float*)d_in[7];
    const float* edge_b   = (const float*)d_in[8];
    const float* out_w    = (const float*)d_in[9];
    const float* out_b    = (const float*)d_in[10];
    float* out = (float*)d_out;

    int E = in_sizes[1];

    // Fused convert + precompute (one launch)
    long long conv_items = (TBL_ELEMS + CONV_PER_THREAD - 1) / CONV_PER_THREAD;
    int conv_blocks = (int)((conv_items + CONV_BLOCK - 1) / CONV_BLOCK);
    convert_kernel<<<conv_blocks, CONV_BLOCK>>>(emb_feats, edge_w, edge_b,
                                                out_w, out_b);

    int threads = 256;
    int warps_per_block = threads / 32;
    int blocks = (E + warps_per_block - 1) / warps_per_block;
    edge_pred_kernel<<<blocks, threads>>>(x, src, dst, neg_dst, msg,
                                          emb_type, out_w, out, E);
}

// round 17
// speedup vs baseline: 1.2358x; 1.0325x over previous
#include <cuda_runtime.h>
#include <cuda_fp16.h>

#define N_FEAT_COLS 9
#define CARD 50000
#define EMB 128
#define EDGE_DIM 27
#define TBL_ELEMS (N_FEAT_COLS * CARD * EMB)   // 57,600,000
#define TBL_COL_BYTES (CARD * EMB * 2)         // 12,800,000 bytes per column table

// fp16 shadow of emb_feats (115.2 MB static device scratch)
__device__ __half g_tbl[TBL_ELEMS];
// fp16 shadow of emb_type (3 x 128)
__device__ __half g_ty[3 * EMB];

__device__ float g_v[EDGE_DIM];
__device__ float g_c;

#define CONV_BLOCK 256
#define CONV_PER_THREAD 4   // floats per thread

// Fused: fp32->fp16 table conversion everywhere; first 4 blocks' warps also
// compute g_v / g_c; block 4 converts emb_type.
__global__ __launch_bounds__(CONV_BLOCK)
void convert_kernel(const float* __restrict__ src,
                    const float* __restrict__ emb_type,
                    const float* __restrict__ edge_w,
                    const float* __restrict__ edge_b,
                    const float* __restrict__ out_w,
                    const float* __restrict__ out_b) {
    if (blockIdx.x < 4) {
        const unsigned FULL = 0xffffffffu;
        int w = (blockIdx.x << 3) + (threadIdx.x >> 5);
        int lane = threadIdx.x & 31;
        if (w <= EDGE_DIM) {
            float s = 0.f;
            if (w < EDGE_DIM) {
                for (int k = lane; k < EMB; k += 32)
                    s += out_w[k] * edge_w[k * EDGE_DIM + w];
            } else {
                for (int k = lane; k < EMB; k += 32)
                    s += out_w[k] * edge_b[k];
            }
            #pragma unroll
            for (int o = 16; o > 0; o >>= 1) s += __shfl_xor_sync(FULL, s, o);
            if (lane == 0) {
                if (w < EDGE_DIM) g_v[w] = s;
                else              g_c = s + out_b[0];
            }
        }
    } else if (blockIdx.x == 4) {
        for (int i = threadIdx.x; i < 3 * EMB; i += CONV_BLOCK)
            g_ty[i] = __float2half_rn(emb_type[i]);
    }
    long long i = ((long long)blockIdx.x * CONV_BLOCK + threadIdx.x) * CONV_PER_THREAD;
    if (i >= TBL_ELEMS) return;
    float4 v = __ldcs(reinterpret_cast<const float4*>(src + i));
    __half2 lo = __floats2half2_rn(v.x, v.y);
    __half2 hi = __floats2half2_rn(v.z, v.w);
    uint2 u;
    u.x = *reinterpret_cast<unsigned*>(&lo);
    u.y = *reinterpret_cast<unsigned*>(&hi);
    *reinterpret_cast<uint2*>(g_tbl + i) = u;
}

__device__ __forceinline__ float4 ld4(const float* __restrict__ p) {
    return *reinterpret_cast<const float4*>(p);
}

__device__ __forceinline__ __half2 u2h(unsigned u) {
    return *reinterpret_cast<__half2*>(&u);
}

// Issue the (up to) 4 table gathers + the type row for one node.
__device__ __forceinline__ void issue_node(uint2* g, uint2& ty,
                                           int t, int h0, int nh,
                                           const int* f, unsigned lane8,
                                           const char* __restrict__ tbl) {
    const uint2 z = make_uint2(0u, 0u);
    #pragma unroll
    for (int i = 0; i < 4; i++) {
        unsigned off = (unsigned)(h0 + i) * (unsigned)TBL_COL_BYTES
                     + ((unsigned)f[i] << 8) + lane8;
        g[i] = (i < nh) ? __ldg(reinterpret_cast<const uint2*>(tbl + off)) : z;
    }
    ty = __ldg(reinterpret_cast<const uint2*>(
             reinterpret_cast<const char*>(g_ty) + (unsigned)t * (EMB * 2) + lane8));
}

// Consume: fp16 tree over 4 gathers + type row, one convert -> float4.
__device__ __forceinline__ float4 consume_node(const uint2* g, uint2 ty) {
    __half2 lo = __hadd2(__hadd2(u2h(g[0].x), u2h(g[1].x)),
                         __hadd2(u2h(g[2].x), u2h(g[3].x)));
    __half2 hi = __hadd2(__hadd2(u2h(g[0].y), u2h(g[1].y)),
                         __hadd2(u2h(g[2].y), u2h(g[3].y)));
    lo = __hadd2(lo, u2h(ty.x));
    hi = __hadd2(hi, u2h(ty.y));
    float2 flo = __half22float2(lo);
    float2 fhi = __half22float2(hi);
    return make_float4(flo.x, flo.y, fhi.x, fhi.y);
}

__global__ __launch_bounds__(256)
void edge_pred_kernel(const int* __restrict__ x,
                      const int* __restrict__ src,
                      const int* __restrict__ dst,
                      const int* __restrict__ neg_dst,
                      const float* __restrict__ msg,
                      const float* __restrict__ out_w,
                      float* __restrict__ out,
                      int E) {
    const unsigned FULL = 0xffffffffu;
    int warp = (blockIdx.x * blockDim.x + threadIdx.x) >> 5;
    int lane = threadIdx.x & 31;
    if (warp >= E) return;
    int e = warp;
    int lane4 = lane * 4;
    unsigned lane8 = (unsigned)lane * 8u;
    const char* tbl = reinterpret_cast<const char*>(g_tbl);

    int s  = __ldcs(src + e);
    int d  = __ldcs(dst + e);
    int nd = __ldcs(neg_dst + e);

    // Lanes 0..29 cooperatively load the three 10-int x rows.
    int which = lane / 10;          // 0:src 1:dst 2:neg
    int off   = lane - which * 10;
    int nid   = (which == 0) ? s : (which == 1) ? d : nd;
    int rv = 0;
    if (lane < 30) rv = __ldcs(x + (long long)nid * 10 + off);

    // msg dot with precomputed v (streaming; independent)
    float m = 0.f;
    if (lane < EDGE_DIM)
        m = __ldcs(msg + (long long)e * EDGE_DIM + lane) * g_v[lane];

    // ---- all types / feature indices up front (shuffles only) ----
    int t0 = __shfl_sync(FULL, rv, 0);
    int t1 = __shfl_sync(FULL, rv, 10);
    int t2 = __shfl_sync(FULL, rv, 20);
    // TYPE_PER_COL = (0,0,0,0,1,2,2,2,2)
    int h00 = (t0 == 0) ? 0 : (t0 == 1) ? 4 : 5;
    int h01 = (t1 == 0) ? 0 : (t1 == 1) ? 4 : 5;
    int h02 = (t2 == 0) ? 0 : (t2 == 1) ? 4 : 5;
    int nh0 = (t0 == 1) ? 1 : 4;
    int nh1 = (t1 == 1) ? 1 : 4;
    int nh2 = (t2 == 1) ? 1 : 4;

    int f0[4], f1[4], f2[4];
    #pragma unroll
    for (int i = 0; i < 4; i++) {
        f0[i] = __shfl_sync(FULL, rv,      h00 + i + 1);
        f1[i] = __shfl_sync(FULL, rv, 10 + h01 + i + 1);
        f2[i] = __shfl_sync(FULL, rv, 20 + h02 + i + 1);
    }

    // ---- two-node-deep pipeline (memory shape unchanged) ----
    uint2 gA[4], gB[4], tyA, tyB, tyC;
    issue_node(gA, tyA, t0, h00, nh0, f0, lane8, tbl);  // node0 in flight
    issue_node(gB, tyB, t1, h01, nh1, f1, lane8, tbl);  // node1 in flight
    float4 a0 = consume_node(gA, tyA);                  // consume node0
    issue_node(gA, tyC, t2, h02, nh2, f2, lane8, tbl);  // node2 in flight
    float4 a1 = consume_node(gB, tyB);                  // consume node1
    float4 a2 = consume_node(gA, tyC);                  // consume node2

    float4 ow = ld4(out_w + lane4);

    float pp = fmaxf(a0.x + a1.x, 0.f) * ow.x
             + fmaxf(a0.y + a1.y, 0.f) * ow.y
             + fmaxf(a0.z + a1.z, 0.f) * ow.z
             + fmaxf(a0.w + a1.w, 0.f) * ow.w;
    float np = fmaxf(a0.x + a2.x, 0.f) * ow.x
             + fmaxf(a0.y + a2.y, 0.f) * ow.y
             + fmaxf(a0.z + a2.z, 0.f) * ow.z
             + fmaxf(a0.w + a2.w, 0.f) * ow.w;

    pp += m;
    np += m;

    // ---- split half-warp reduction: lanes 0..15 reduce pp, 16..31 reduce np
    pp += __shfl_xor_sync(FULL, pp, 16);
    np += __shfl_xor_sync(FULL, np, 16);
    float v = (lane < 16) ? pp : np;
    #pragma unroll
    for (int o = 8; o > 0; o >>= 1)
        v += __shfl_xor_sync(FULL, v, o);

    if (lane == 0)  out[e]     = v + g_c;   // pos
    if (lane == 16) out[E + e] = v + g_c;   // neg
}

extern "C" void kernel_launch(void* const* d_in, const int* in_sizes, int n_in,
                              void* d_out, int out_size) {
    const int*   x        = (const int*)  d_in[0];
    const int*   src      = (const int*)  d_in[1];
    const int*   dst      = (const int*)  d_in[2];
    const int*   neg_dst  = (const int*)  d_in[3];
    const float* msg      = (const float*)d_in[4];
    const float* emb_type = (const float*)d_in[5];
    const float* emb_feats= (const float*)d_in[6];
    const float* edge_w   = (const float*)d_in[7];
    const float* edge_b   = (const float*)d_in[8];
    const float* out_w    = (const float*)d_in[9];
    const float* out_b    = (const float*)d_in[10];
    float* out = (float*)d_out;

    int E = in_sizes[1];

    // Fused convert + precompute (one launch)
    long long conv_items = (TBL_ELEMS + CONV_PER_THREAD - 1) / CONV_PER_THREAD;
    int conv_blocks = (int)((conv_items + CONV_BLOCK - 1) / CONV_BLOCK);
    convert_kernel<<<conv_blocks, CONV_BLOCK>>>(emb_feats, emb_type,
                                                edge_w, edge_b, out_w, out_b);

    int threads = 256;
    int warps_per_block = threads / 32;
    int blocks = (E + warps_per_block - 1) / warps_per_block;
    edge_pred_kernel<<<blocks, threads>>>(x, src, dst, neg_dst, msg,
                                          out_w, out, E);
}